// round 1
// baseline (speedup 1.0000x reference)
#include <cuda_runtime.h>
#include <stdint.h>

#define N_NODES 50000
#define E_EDGES 800000
#define D 128
#define ROWS_PER_BLOCK 16

// Scratch (no allocations allowed) — ~102 MB total.
__device__ float g_Wh0[(size_t)N_NODES * D];
__device__ float g_Wh1[(size_t)N_NODES * D];
__device__ float g_acc0[(size_t)N_NODES * D];
__device__ float g_acc1[(size_t)N_NODES * D];
__device__ float g_cnt0[N_NODES];
__device__ float g_cnt1[N_NODES];

// ---------------------------------------------------------------------------
// Zero the accumulators and counters (poisoned scratch each launch).
// ---------------------------------------------------------------------------
__global__ void zero_kernel() {
    const size_t stride = (size_t)gridDim.x * blockDim.x;
    size_t idx = (size_t)blockIdx.x * blockDim.x + threadIdx.x;
    const size_t total4 = (size_t)N_NODES * D / 4;
    float4 z = make_float4(0.f, 0.f, 0.f, 0.f);
    for (size_t i = idx; i < total4; i += stride) {
        reinterpret_cast<float4*>(g_acc0)[i] = z;
        reinterpret_cast<float4*>(g_acc1)[i] = z;
    }
    for (size_t i = idx; i < N_NODES; i += stride) {
        g_cnt0[i] = 0.f;
        g_cnt1[i] = 0.f;
    }
}

// ---------------------------------------------------------------------------
// Wh = feat @ W + b for both relations (blockIdx.y selects relation).
// 128 threads; each block does 16 node rows. feat tile in smem, W columns
// streamed (hot in L2 after the first wave), 16 register accumulators.
// ---------------------------------------------------------------------------
__global__ __launch_bounds__(128) void gemm_kernel(
    const float* __restrict__ feat,
    const float* __restrict__ W0, const float* __restrict__ b0,
    const float* __restrict__ W1, const float* __restrict__ b1)
{
    const int rel = blockIdx.y;
    const float* __restrict__ W = rel ? W1 : W0;
    const float* __restrict__ b = rel ? b1 : b0;
    float* __restrict__ Wh = rel ? g_Wh1 : g_Wh0;

    __shared__ float sf[ROWS_PER_BLOCK][D];
    const int tid = threadIdx.x;
    const int row0 = blockIdx.x * ROWS_PER_BLOCK;

#pragma unroll
    for (int r = 0; r < ROWS_PER_BLOCK; r++)
        sf[r][tid] = feat[(size_t)(row0 + r) * D + tid];
    __syncthreads();

    float acc[ROWS_PER_BLOCK];
#pragma unroll
    for (int r = 0; r < ROWS_PER_BLOCK; r++) acc[r] = 0.f;

#pragma unroll 4
    for (int k = 0; k < D; k++) {
        const float w = W[(size_t)k * D + tid];
#pragma unroll
        for (int r = 0; r < ROWS_PER_BLOCK; r++)
            acc[r] = fmaf(sf[r][k], w, acc[r]);
    }

    const float bias = b[tid];
#pragma unroll
    for (int r = 0; r < ROWS_PER_BLOCK; r++)
        Wh[(size_t)(row0 + r) * D + tid] = acc[r] + bias;
}

// ---------------------------------------------------------------------------
// Warp-per-edge scatter: gather Wh[src] (float4/lane, coalesced) and
// atomicAdd into acc[dst]; lane 0 bumps the in-degree counter.
// blockIdx.y selects relation.
// ---------------------------------------------------------------------------
__global__ __launch_bounds__(256) void scatter_kernel(
    const int* __restrict__ src0, const int* __restrict__ dst0,
    const int* __restrict__ src1, const int* __restrict__ dst1)
{
    const int rel = blockIdx.y;
    const int* __restrict__ src = rel ? src1 : src0;
    const int* __restrict__ dst = rel ? dst1 : dst0;
    const float* __restrict__ Wh = rel ? g_Wh1 : g_Wh0;
    float* __restrict__ acc = rel ? g_acc1 : g_acc0;
    float* __restrict__ cnt = rel ? g_cnt1 : g_cnt0;

    const int warps_per_block = blockDim.x >> 5;
    const int e = blockIdx.x * warps_per_block + (threadIdx.x >> 5);
    const int lane = threadIdx.x & 31;
    if (e >= E_EDGES) return;

    const int s = src[e];
    const int d = dst[e];

    const float4 v =
        reinterpret_cast<const float4*>(Wh + (size_t)s * D)[lane];
    float* a = acc + (size_t)d * D + lane * 4;
    atomicAdd(a + 0, v.x);
    atomicAdd(a + 1, v.y);
    atomicAdd(a + 2, v.z);
    atomicAdd(a + 3, v.w);
    if (lane == 0) atomicAdd(cnt + d, 1.0f);
}

// ---------------------------------------------------------------------------
// out[n] = acc0[n]/max(cnt0[n],1) + acc1[n]/max(cnt1[n],1)
// ---------------------------------------------------------------------------
__global__ __launch_bounds__(256) void finalize_kernel(float* __restrict__ out) {
    const size_t idx = (size_t)blockIdx.x * blockDim.x + threadIdx.x;
    if (idx >= (size_t)N_NODES * D) return;
    const int n = (int)(idx >> 7);
    const float inv0 = 1.0f / fmaxf(g_cnt0[n], 1.0f);
    const float inv1 = 1.0f / fmaxf(g_cnt1[n], 1.0f);
    out[idx] = g_acc0[idx] * inv0 + g_acc1[idx] * inv1;
}

// ---------------------------------------------------------------------------
// inputs (metadata order): feat, W0, b0, W1, b1, src0, dst0, src1, dst1
// ---------------------------------------------------------------------------
extern "C" void kernel_launch(void* const* d_in, const int* in_sizes, int n_in,
                              void* d_out, int out_size) {
    const float* feat = (const float*)d_in[0];
    const float* W0   = (const float*)d_in[1];
    const float* b0   = (const float*)d_in[2];
    const float* W1   = (const float*)d_in[3];
    const float* b1   = (const float*)d_in[4];
    const int*   src0 = (const int*)d_in[5];
    const int*   dst0 = (const int*)d_in[6];
    const int*   src1 = (const int*)d_in[7];
    const int*   dst1 = (const int*)d_in[8];
    float* out = (float*)d_out;

    zero_kernel<<<592, 256>>>();

    dim3 ggrid(N_NODES / ROWS_PER_BLOCK, 2);   // 50000 divisible by 16 -> 3125
    gemm_kernel<<<ggrid, 128>>>(feat, W0, b0, W1, b1);

    const int warps_per_block = 8;              // 256 threads
    dim3 sgrid((E_EDGES + warps_per_block - 1) / warps_per_block, 2);
    scatter_kernel<<<sgrid, 256>>>(src0, dst0, src1, dst1);

    const int total = N_NODES * D;
    finalize_kernel<<<(total + 255) / 256, 256>>>(out);
}

// round 2
// speedup vs baseline: 2.1595x; 2.1595x over previous
#include <cuda_runtime.h>
#include <stdint.h>

#define N_NODES 50000
#define E_EDGES 800000
#define D 128
#define GROWS 32           // node rows per GEMM block

// ---------------------------------------------------------------------------
// Scratch (__device__ globals; no allocations allowed). ~58 MB total.
// ---------------------------------------------------------------------------
__device__ float g_Wh0[(size_t)N_NODES * D];
__device__ float g_Wh1[(size_t)N_NODES * D];
__device__ int   g_cnt0[N_NODES];
__device__ int   g_cnt1[N_NODES];
__device__ int   g_offs0[N_NODES + 1];
__device__ int   g_offs1[N_NODES + 1];
__device__ int   g_cur0[N_NODES];
__device__ int   g_cur1[N_NODES];
__device__ int   g_srt0[E_EDGES];   // src ids sorted by dst
__device__ int   g_srt1[E_EDGES];

// ---------------------------------------------------------------------------
// f32x2 packed-FMA helpers (Blackwell-only; FFMA2 reachable only via PTX).
// ---------------------------------------------------------------------------
__device__ __forceinline__ unsigned long long pack2(float lo, float hi) {
    unsigned long long r;
    asm("mov.b64 %0, {%1, %2};" : "=l"(r) : "f"(lo), "f"(hi));
    return r;
}
__device__ __forceinline__ void fma2(unsigned long long& d,
                                     unsigned long long a,
                                     unsigned long long b) {
    asm("fma.rn.f32x2 %0, %1, %2, %0;" : "+l"(d) : "l"(a), "l"(b));
}
__device__ __forceinline__ float2 unpack2(unsigned long long v) {
    float2 f;
    asm("mov.b64 {%0, %1}, %2;" : "=f"(f.x), "=f"(f.y) : "l"(v));
    return f;
}

// ---------------------------------------------------------------------------
// Zero the per-relation degree counters.
// ---------------------------------------------------------------------------
__global__ void zero_cnt_kernel() {
    int i = blockIdx.x * blockDim.x + threadIdx.x;
    if (i < N_NODES) { g_cnt0[i] = 0; g_cnt1[i] = 0; }
}

// ---------------------------------------------------------------------------
// Wh = feat @ W + b, both relations (blockIdx.y). 128 threads, 32 rows/block.
// feat tile transposed in smem; each thread owns one output column and 16
// packed row-pair accumulators; inner loop is LDS.64 (broadcast) + f32x2 FMA.
// ---------------------------------------------------------------------------
__global__ __launch_bounds__(128) void gemm_kernel(
    const float* __restrict__ feat,
    const float* __restrict__ W0, const float* __restrict__ b0,
    const float* __restrict__ W1, const float* __restrict__ b1)
{
    const int rel = blockIdx.y;
    const float* __restrict__ W = rel ? W1 : W0;
    const float* __restrict__ b = rel ? b1 : b0;
    float* __restrict__ Wh = rel ? g_Wh1 : g_Wh0;

    __shared__ __align__(16) float sft[D][GROWS + 2];   // [k][row], pad keeps 8B align
    const int tid  = threadIdx.x;
    const int row0 = blockIdx.x * GROWS;

    // Load 32 rows x 128 cols of feat, transposing into smem.
    for (int i = tid; i < GROWS * (D / 4); i += 128) {
        const int r  = i >> 5;          // local row 0..31
        const int c4 = i & 31;          // float4 index along k
        const int grow = row0 + r;
        float4 v = make_float4(0.f, 0.f, 0.f, 0.f);
        if (grow < N_NODES)
            v = reinterpret_cast<const float4*>(feat + (size_t)grow * D)[c4];
        sft[4 * c4 + 0][r] = v.x;
        sft[4 * c4 + 1][r] = v.y;
        sft[4 * c4 + 2][r] = v.z;
        sft[4 * c4 + 3][r] = v.w;
    }
    __syncthreads();

    unsigned long long acc[16];
#pragma unroll
    for (int r = 0; r < 16; r++) acc[r] = 0ull;

    const float* __restrict__ Wcol = W + tid;
#pragma unroll 4
    for (int k = 0; k < D; k++) {
        const float w = __ldg(Wcol + (size_t)k * D);
        const unsigned long long w2 = pack2(w, w);
        const unsigned long long* arow =
            reinterpret_cast<const unsigned long long*>(&sft[k][0]);
#pragma unroll
        for (int r = 0; r < 16; r++)
            fma2(acc[r], arow[r], w2);
    }

    const float bias = __ldg(b + tid);
#pragma unroll
    for (int r = 0; r < 16; r++) {
        const float2 v = unpack2(acc[r]);
        const int g0 = row0 + 2 * r;
        if (g0 < N_NODES)     Wh[(size_t)g0 * D + tid]       = v.x + bias;
        if (g0 + 1 < N_NODES) Wh[(size_t)(g0 + 1) * D + tid] = v.y + bias;
    }
}

// ---------------------------------------------------------------------------
// Per-dst histogram (both relations via blockIdx.y).
// ---------------------------------------------------------------------------
__global__ __launch_bounds__(256) void hist_kernel(
    const int* __restrict__ dst0, const int* __restrict__ dst1)
{
    const int e = blockIdx.x * blockDim.x + threadIdx.x;
    if (e >= E_EDGES) return;
    if (blockIdx.y == 0) atomicAdd(&g_cnt0[dst0[e]], 1);
    else                 atomicAdd(&g_cnt1[dst1[e]], 1);
}

// ---------------------------------------------------------------------------
// Single-block exclusive scan of both count arrays -> offs + fill cursors.
// ---------------------------------------------------------------------------
__device__ __forceinline__ void scan_step(
    const int* __restrict__ cnt, int* __restrict__ offs, int* __restrict__ cur,
    int& carry, int base, int lane, int wid, int* wsum)
{
    const int i = base + threadIdx.x;
    const int x = (i < N_NODES) ? cnt[i] : 0;
    int s = x;
#pragma unroll
    for (int o = 1; o < 32; o <<= 1) {
        int t = __shfl_up_sync(0xffffffffu, s, o);
        if (lane >= o) s += t;
    }
    if (lane == 31) wsum[wid] = s;
    __syncthreads();
    if (wid == 0) {
        int t = wsum[lane];
#pragma unroll
        for (int o = 1; o < 32; o <<= 1) {
            int u = __shfl_up_sync(0xffffffffu, t, o);
            if (lane >= o) t += u;
        }
        wsum[lane] = t;
    }
    __syncthreads();
    const int prefix = (wid > 0) ? wsum[wid - 1] : 0;
    const int excl = carry + prefix + s - x;
    if (i < N_NODES) { offs[i] = excl; cur[i] = excl; }
    carry += wsum[31];
    __syncthreads();   // before wsum reuse
}

__global__ __launch_bounds__(1024) void scan_kernel() {
    __shared__ int wsum[32];
    const int lane = threadIdx.x & 31;
    const int wid  = threadIdx.x >> 5;
    int carry0 = 0, carry1 = 0;
    for (int base = 0; base < N_NODES; base += 1024) {
        scan_step(g_cnt0, g_offs0, g_cur0, carry0, base, lane, wid, wsum);
        scan_step(g_cnt1, g_offs1, g_cur1, carry1, base, lane, wid, wsum);
    }
    if (threadIdx.x == 0) { g_offs0[N_NODES] = E_EDGES; g_offs1[N_NODES] = E_EDGES; }
}

// ---------------------------------------------------------------------------
// Fill sorted-by-dst src lists.
// ---------------------------------------------------------------------------
__global__ __launch_bounds__(256) void fill_kernel(
    const int* __restrict__ src0, const int* __restrict__ dst0,
    const int* __restrict__ src1, const int* __restrict__ dst1)
{
    const int e = blockIdx.x * blockDim.x + threadIdx.x;
    if (e >= E_EDGES) return;
    if (blockIdx.y == 0) {
        const int p = atomicAdd(&g_cur0[dst0[e]], 1);
        g_srt0[p] = src0[e];
    } else {
        const int p = atomicAdd(&g_cur1[dst1[e]], 1);
        g_srt1[p] = src1[e];
    }
}

// ---------------------------------------------------------------------------
// Warp-per-node pull gather: mean over in-edges for both relations, summed,
// written straight to out. Unrolled x4 for memory-level parallelism.
// ---------------------------------------------------------------------------
__device__ __forceinline__ float4 ld_row4(const float* __restrict__ Wh,
                                          int s, int lane) {
    return __ldg(reinterpret_cast<const float4*>(Wh + (size_t)s * D) + lane);
}

__device__ __forceinline__ float4 gather_rel(
    const float* __restrict__ Wh, const int* __restrict__ srt,
    int beg, int end, int lane)
{
    float4 acc = make_float4(0.f, 0.f, 0.f, 0.f);
    int e = beg;
    for (; e + 4 <= end; e += 4) {
        const int s0 = __ldg(srt + e), s1 = __ldg(srt + e + 1);
        const int s2 = __ldg(srt + e + 2), s3 = __ldg(srt + e + 3);
        const float4 v0 = ld_row4(Wh, s0, lane);
        const float4 v1 = ld_row4(Wh, s1, lane);
        const float4 v2 = ld_row4(Wh, s2, lane);
        const float4 v3 = ld_row4(Wh, s3, lane);
        acc.x += (v0.x + v1.x) + (v2.x + v3.x);
        acc.y += (v0.y + v1.y) + (v2.y + v3.y);
        acc.z += (v0.z + v1.z) + (v2.z + v3.z);
        acc.w += (v0.w + v1.w) + (v2.w + v3.w);
    }
    for (; e < end; e++) {
        const float4 v = ld_row4(Wh, __ldg(srt + e), lane);
        acc.x += v.x; acc.y += v.y; acc.z += v.z; acc.w += v.w;
    }
    return acc;
}

__global__ __launch_bounds__(256) void gather_kernel(float* __restrict__ out) {
    const int n = blockIdx.x * 8 + (threadIdx.x >> 5);
    if (n >= N_NODES) return;
    const int lane = threadIdx.x & 31;

    const int b0 = g_offs0[n], e0 = g_offs0[n + 1];
    const int b1 = g_offs1[n], e1 = g_offs1[n + 1];

    float4 a0 = gather_rel(g_Wh0, g_srt0, b0, e0, lane);
    float4 a1 = gather_rel(g_Wh1, g_srt1, b1, e1, lane);

    const float inv0 = 1.0f / fmaxf((float)(e0 - b0), 1.0f);
    const float inv1 = 1.0f / fmaxf((float)(e1 - b1), 1.0f);

    float4 r;
    r.x = a0.x * inv0 + a1.x * inv1;
    r.y = a0.y * inv0 + a1.y * inv1;
    r.z = a0.z * inv0 + a1.z * inv1;
    r.w = a0.w * inv0 + a1.w * inv1;
    reinterpret_cast<float4*>(out + (size_t)n * D)[lane] = r;
}

// ---------------------------------------------------------------------------
// inputs: feat, W0, b0, W1, b1, src0, dst0, src1, dst1
// ---------------------------------------------------------------------------
extern "C" void kernel_launch(void* const* d_in, const int* in_sizes, int n_in,
                              void* d_out, int out_size) {
    const float* feat = (const float*)d_in[0];
    const float* W0   = (const float*)d_in[1];
    const float* b0   = (const float*)d_in[2];
    const float* W1   = (const float*)d_in[3];
    const float* b1   = (const float*)d_in[4];
    const int*   src0 = (const int*)d_in[5];
    const int*   dst0 = (const int*)d_in[6];
    const int*   src1 = (const int*)d_in[7];
    const int*   dst1 = (const int*)d_in[8];
    float* out = (float*)d_out;

    zero_cnt_kernel<<<(N_NODES + 255) / 256, 256>>>();

    dim3 egrid((E_EDGES + 255) / 256, 2);
    hist_kernel<<<egrid, 256>>>(dst0, dst1);

    scan_kernel<<<1, 1024>>>();

    fill_kernel<<<egrid, 256>>>(src0, dst0, src1, dst1);

    dim3 ggrid((N_NODES + GROWS - 1) / GROWS, 2);   // 1563 x 2
    gemm_kernel<<<ggrid, 128>>>(feat, W0, b0, W1, b1);

    gather_kernel<<<(N_NODES + 7) / 8, 256>>>(out);
}

// round 3
// speedup vs baseline: 3.1148x; 1.4424x over previous
#include <cuda_runtime.h>
#include <stdint.h>

#define N_NODES 50000
#define E_EDGES 800000
#define D 128
#define GROWS 32
#define SCAN_B 512
#define NBLK ((N_NODES + SCAN_B - 1) / SCAN_B)   // 98

// ---------------------------------------------------------------------------
// Scratch (__device__ globals; no allocations allowed).
// ---------------------------------------------------------------------------
__device__ float g_Wh0[(size_t)N_NODES * D];
__device__ float g_Wh1[(size_t)N_NODES * D];
__device__ int   g_cnt0[N_NODES];
__device__ int   g_cnt1[N_NODES];
__device__ int   g_offs0[N_NODES + 1];
__device__ int   g_offs1[N_NODES + 1];
__device__ int   g_cur0[N_NODES];
__device__ int   g_cur1[N_NODES];
__device__ int   g_srt0[E_EDGES];
__device__ int   g_srt1[E_EDGES];
__device__ int   g_bsum0[NBLK];
__device__ int   g_bsum1[NBLK];

// ---------------------------------------------------------------------------
// Host-side stream/event resources, created once at static-init time
// (host resources only; all captured work is identical on every call).
// ---------------------------------------------------------------------------
struct SideStream {
    cudaStream_t s;
    cudaEvent_t  fork, join;
    SideStream() {
        cudaStreamCreateWithFlags(&s, cudaStreamNonBlocking);
        cudaEventCreateWithFlags(&fork, cudaEventDisableTiming);
        cudaEventCreateWithFlags(&join, cudaEventDisableTiming);
    }
};
static SideStream g_ss;

// ---------------------------------------------------------------------------
// f32x2 packed-FMA helpers (Blackwell FFMA2, PTX-only).
// ---------------------------------------------------------------------------
__device__ __forceinline__ unsigned long long pack2(float lo, float hi) {
    unsigned long long r;
    asm("mov.b64 %0, {%1, %2};" : "=l"(r) : "f"(lo), "f"(hi));
    return r;
}
__device__ __forceinline__ void fma2(unsigned long long& d,
                                     unsigned long long a,
                                     unsigned long long b) {
    asm("fma.rn.f32x2 %0, %1, %2, %0;" : "+l"(d) : "l"(a), "l"(b));
}
__device__ __forceinline__ float2 unpack2(unsigned long long v) {
    float2 f;
    asm("mov.b64 {%0, %1}, %2;" : "=f"(f.x), "=f"(f.y) : "l"(v));
    return f;
}

// ---------------------------------------------------------------------------
// GEMM: Wh = feat @ W + b, both relations (blockIdx.y). Runs on side stream.
// ---------------------------------------------------------------------------
__global__ __launch_bounds__(128) void gemm_kernel(
    const float* __restrict__ feat,
    const float* __restrict__ W0, const float* __restrict__ b0,
    const float* __restrict__ W1, const float* __restrict__ b1)
{
    const int rel = blockIdx.y;
    const float* __restrict__ W = rel ? W1 : W0;
    const float* __restrict__ b = rel ? b1 : b0;
    float* __restrict__ Wh = rel ? g_Wh1 : g_Wh0;

    __shared__ __align__(16) float sft[D][GROWS + 2];
    const int tid  = threadIdx.x;
    const int row0 = blockIdx.x * GROWS;

    for (int i = tid; i < GROWS * (D / 4); i += 128) {
        const int r  = i >> 5;
        const int c4 = i & 31;
        const int grow = row0 + r;
        float4 v = make_float4(0.f, 0.f, 0.f, 0.f);
        if (grow < N_NODES)
            v = reinterpret_cast<const float4*>(feat + (size_t)grow * D)[c4];
        sft[4 * c4 + 0][r] = v.x;
        sft[4 * c4 + 1][r] = v.y;
        sft[4 * c4 + 2][r] = v.z;
        sft[4 * c4 + 3][r] = v.w;
    }
    __syncthreads();

    unsigned long long acc[16];
#pragma unroll
    for (int r = 0; r < 16; r++) acc[r] = 0ull;

    const float* __restrict__ Wcol = W + tid;
#pragma unroll 4
    for (int k = 0; k < D; k++) {
        const float w = __ldg(Wcol + (size_t)k * D);
        const unsigned long long w2 = pack2(w, w);
        const unsigned long long* arow =
            reinterpret_cast<const unsigned long long*>(&sft[k][0]);
#pragma unroll
        for (int r = 0; r < 16; r++)
            fma2(acc[r], arow[r], w2);
    }

    const float bias = __ldg(b + tid);
#pragma unroll
    for (int r = 0; r < 16; r++) {
        const float2 v = unpack2(acc[r]);
        const int g0 = row0 + 2 * r;
        if (g0 < N_NODES)     Wh[(size_t)g0 * D + tid]       = v.x + bias;
        if (g0 + 1 < N_NODES) Wh[(size_t)(g0 + 1) * D + tid] = v.y + bias;
    }
}

// ---------------------------------------------------------------------------
// Histogram of dst per relation.
// ---------------------------------------------------------------------------
__global__ __launch_bounds__(256) void hist_kernel(
    const int* __restrict__ dst0, const int* __restrict__ dst1)
{
    const int e = blockIdx.x * blockDim.x + threadIdx.x;
    if (e >= E_EDGES) return;
    if (blockIdx.y == 0) atomicAdd(&g_cnt0[dst0[e]], 1);
    else                 atomicAdd(&g_cnt1[dst1[e]], 1);
}

// ---------------------------------------------------------------------------
// Parallel scan, phase 1: per-block sums of counts.
// ---------------------------------------------------------------------------
__global__ __launch_bounds__(SCAN_B) void scan1_kernel() {
    const int rel = blockIdx.y;
    const int* __restrict__ cnt = rel ? g_cnt1 : g_cnt0;
    int* __restrict__ bsum = rel ? g_bsum1 : g_bsum0;

    const int i = blockIdx.x * SCAN_B + threadIdx.x;
    int x = (i < N_NODES) ? cnt[i] : 0;
#pragma unroll
    for (int o = 16; o; o >>= 1) x += __shfl_down_sync(0xffffffffu, x, o);

    __shared__ int ws[SCAN_B / 32];
    const int lane = threadIdx.x & 31, wid = threadIdx.x >> 5;
    if (lane == 0) ws[wid] = x;
    __syncthreads();
    if (wid == 0) {
        int t = (lane < SCAN_B / 32) ? ws[lane] : 0;
#pragma unroll
        for (int o = 16; o; o >>= 1) t += __shfl_down_sync(0xffffffffu, t, o);
        if (lane == 0) bsum[blockIdx.x] = t;
    }
}

// ---------------------------------------------------------------------------
// Phase 2: exclusive scan of the NBLK block sums (one block per relation).
// ---------------------------------------------------------------------------
__global__ __launch_bounds__(128) void scan2_kernel() {
    int* __restrict__ bsum = blockIdx.x ? g_bsum1 : g_bsum0;
    __shared__ int buf[128];
    const int tid = threadIdx.x;
    const int x = (tid < NBLK) ? bsum[tid] : 0;
    buf[tid] = x;
    __syncthreads();
#pragma unroll
    for (int o = 1; o < 128; o <<= 1) {
        int v = (tid >= o) ? buf[tid - o] : 0;
        __syncthreads();
        buf[tid] += v;
        __syncthreads();
    }
    if (tid < NBLK) bsum[tid] = buf[tid] - x;   // exclusive
}

// ---------------------------------------------------------------------------
// Phase 3: local exclusive scan + block offset -> offs, cur.
// ---------------------------------------------------------------------------
__global__ __launch_bounds__(SCAN_B) void scan3_kernel() {
    const int rel = blockIdx.y;
    const int* __restrict__ cnt = rel ? g_cnt1 : g_cnt0;
    const int* __restrict__ bsum = rel ? g_bsum1 : g_bsum0;
    int* __restrict__ offs = rel ? g_offs1 : g_offs0;
    int* __restrict__ cur  = rel ? g_cur1  : g_cur0;

    const int i = blockIdx.x * SCAN_B + threadIdx.x;
    const int x = (i < N_NODES) ? cnt[i] : 0;
    const int lane = threadIdx.x & 31, wid = threadIdx.x >> 5;

    int s = x;
#pragma unroll
    for (int o = 1; o < 32; o <<= 1) {
        int t = __shfl_up_sync(0xffffffffu, s, o);
        if (lane >= o) s += t;
    }
    __shared__ int ws[SCAN_B / 32];
    if (lane == 31) ws[wid] = s;
    __syncthreads();
    if (wid == 0) {
        int t = (lane < SCAN_B / 32) ? ws[lane] : 0;
#pragma unroll
        for (int o = 1; o < 32; o <<= 1) {
            int u = __shfl_up_sync(0xffffffffu, t, o);
            if (lane >= o) t += u;
        }
        if (lane < SCAN_B / 32) ws[lane] = t;
    }
    __syncthreads();
    const int prefix = (wid > 0) ? ws[wid - 1] : 0;
    const int excl = bsum[blockIdx.x] + prefix + s - x;
    if (i < N_NODES) { offs[i] = excl; cur[i] = excl; }
    if (i == N_NODES - 1) offs[N_NODES] = E_EDGES;
}

// ---------------------------------------------------------------------------
// Fill sorted-by-dst src lists.
// ---------------------------------------------------------------------------
__global__ __launch_bounds__(256) void fill_kernel(
    const int* __restrict__ src0, const int* __restrict__ dst0,
    const int* __restrict__ src1, const int* __restrict__ dst1)
{
    const int e = blockIdx.x * blockDim.x + threadIdx.x;
    if (e >= E_EDGES) return;
    if (blockIdx.y == 0) {
        const int p = atomicAdd(&g_cur0[dst0[e]], 1);
        g_srt0[p] = src0[e];
    } else {
        const int p = atomicAdd(&g_cur1[dst1[e]], 1);
        g_srt1[p] = src1[e];
    }
}

// ---------------------------------------------------------------------------
// Warp-per-node pull gather.
// ---------------------------------------------------------------------------
__device__ __forceinline__ float4 ld_row4(const float* __restrict__ Wh,
                                          int s, int lane) {
    return __ldg(reinterpret_cast<const float4*>(Wh + (size_t)s * D) + lane);
}

__device__ __forceinline__ float4 gather_rel(
    const float* __restrict__ Wh, const int* __restrict__ srt,
    int beg, int end, int lane)
{
    float4 acc = make_float4(0.f, 0.f, 0.f, 0.f);
    int e = beg;
    for (; e + 4 <= end; e += 4) {
        const int s0 = __ldg(srt + e),     s1 = __ldg(srt + e + 1);
        const int s2 = __ldg(srt + e + 2), s3 = __ldg(srt + e + 3);
        const float4 v0 = ld_row4(Wh, s0, lane);
        const float4 v1 = ld_row4(Wh, s1, lane);
        const float4 v2 = ld_row4(Wh, s2, lane);
        const float4 v3 = ld_row4(Wh, s3, lane);
        acc.x += (v0.x + v1.x) + (v2.x + v3.x);
        acc.y += (v0.y + v1.y) + (v2.y + v3.y);
        acc.z += (v0.z + v1.z) + (v2.z + v3.z);
        acc.w += (v0.w + v1.w) + (v2.w + v3.w);
    }
    for (; e < end; e++) {
        const float4 v = ld_row4(Wh, __ldg(srt + e), lane);
        acc.x += v.x; acc.y += v.y; acc.z += v.z; acc.w += v.w;
    }
    return acc;
}

__global__ __launch_bounds__(256) void gather_kernel(float* __restrict__ out) {
    const int n = blockIdx.x * 8 + (threadIdx.x >> 5);
    if (n >= N_NODES) return;
    const int lane = threadIdx.x & 31;

    const int b0 = g_offs0[n], e0 = g_offs0[n + 1];
    const int b1 = g_offs1[n], e1 = g_offs1[n + 1];

    float4 a0 = gather_rel(g_Wh0, g_srt0, b0, e0, lane);
    float4 a1 = gather_rel(g_Wh1, g_srt1, b1, e1, lane);

    const float inv0 = 1.0f / fmaxf((float)(e0 - b0), 1.0f);
    const float inv1 = 1.0f / fmaxf((float)(e1 - b1), 1.0f);

    float4 r;
    r.x = a0.x * inv0 + a1.x * inv1;
    r.y = a0.y * inv0 + a1.y * inv1;
    r.z = a0.z * inv0 + a1.z * inv1;
    r.w = a0.w * inv0 + a1.w * inv1;
    reinterpret_cast<float4*>(out + (size_t)n * D)[lane] = r;
}

// ---------------------------------------------------------------------------
// inputs: feat, W0, b0, W1, b1, src0, dst0, src1, dst1
// ---------------------------------------------------------------------------
extern "C" void kernel_launch(void* const* d_in, const int* in_sizes, int n_in,
                              void* d_out, int out_size) {
    const float* feat = (const float*)d_in[0];
    const float* W0   = (const float*)d_in[1];
    const float* b0   = (const float*)d_in[2];
    const float* W1   = (const float*)d_in[3];
    const float* b1   = (const float*)d_in[4];
    const int*   src0 = (const int*)d_in[5];
    const int*   dst0 = (const int*)d_in[6];
    const int*   src1 = (const int*)d_in[7];
    const int*   dst1 = (const int*)d_in[8];
    float* out = (float*)d_out;

    // Fork: GEMM on the side stream, concurrent with the CSR build.
    cudaEventRecord(g_ss.fork, 0);
    cudaStreamWaitEvent(g_ss.s, g_ss.fork, 0);
    dim3 ggrid((N_NODES + GROWS - 1) / GROWS, 2);
    gemm_kernel<<<ggrid, 128, 0, g_ss.s>>>(feat, W0, b0, W1, b1);
    cudaEventRecord(g_ss.join, g_ss.s);

    // Main stream: CSR build.
    void* cnt0_addr = nullptr; void* cnt1_addr = nullptr;
    cudaGetSymbolAddress(&cnt0_addr, g_cnt0);
    cudaGetSymbolAddress(&cnt1_addr, g_cnt1);
    cudaMemsetAsync(cnt0_addr, 0, N_NODES * sizeof(int), 0);
    cudaMemsetAsync(cnt1_addr, 0, N_NODES * sizeof(int), 0);

    dim3 egrid((E_EDGES + 255) / 256, 2);
    hist_kernel<<<egrid, 256>>>(dst0, dst1);

    dim3 sgrid(NBLK, 2);
    scan1_kernel<<<sgrid, SCAN_B>>>();
    scan2_kernel<<<2, 128>>>();
    scan3_kernel<<<sgrid, SCAN_B>>>();

    fill_kernel<<<egrid, 256>>>(src0, dst0, src1, dst1);

    // Join, then gather.
    cudaStreamWaitEvent(0, g_ss.join, 0);
    gather_kernel<<<(N_NODES + 7) / 8, 256>>>(out);
}

// round 4
// speedup vs baseline: 3.3902x; 1.0884x over previous
#include <cuda_runtime.h>
#include <cuda_fp16.h>
#include <stdint.h>

#define N_NODES 50000
#define E_EDGES 800000
#define D 128
#define GROWS 32
#define SCAN_B 512
#define NBLK ((N_NODES + SCAN_B - 1) / SCAN_B)   // 98

// ---------------------------------------------------------------------------
// Scratch (__device__ globals; no allocations allowed).
// ---------------------------------------------------------------------------
__device__ __half g_Wh0[(size_t)N_NODES * D];   // fp16 Wh (halves gather traffic)
__device__ __half g_Wh1[(size_t)N_NODES * D];
__device__ int   g_cnt0[N_NODES];
__device__ int   g_cnt1[N_NODES];
__device__ int   g_offs0[N_NODES + 1];
__device__ int   g_offs1[N_NODES + 1];
__device__ int   g_cur0[N_NODES];
__device__ int   g_cur1[N_NODES];
__device__ int   g_srt0[E_EDGES];
__device__ int   g_srt1[E_EDGES];
__device__ int   g_bsum0[NBLK];
__device__ int   g_bsum1[NBLK];

// ---------------------------------------------------------------------------
// Host-side stream/event resources (created once; host-only resources).
// ---------------------------------------------------------------------------
struct SideStream {
    cudaStream_t s;
    cudaEvent_t  fork, join;
    SideStream() {
        cudaStreamCreateWithFlags(&s, cudaStreamNonBlocking);
        cudaEventCreateWithFlags(&fork, cudaEventDisableTiming);
        cudaEventCreateWithFlags(&join, cudaEventDisableTiming);
    }
};
static SideStream g_ss;

// ---------------------------------------------------------------------------
// f32x2 packed-FMA helpers (Blackwell FFMA2, PTX-only).
// ---------------------------------------------------------------------------
__device__ __forceinline__ unsigned long long pack2(float lo, float hi) {
    unsigned long long r;
    asm("mov.b64 %0, {%1, %2};" : "=l"(r) : "f"(lo), "f"(hi));
    return r;
}
__device__ __forceinline__ void fma2(unsigned long long& d,
                                     unsigned long long a,
                                     unsigned long long b) {
    asm("fma.rn.f32x2 %0, %1, %2, %0;" : "+l"(d) : "l"(a), "l"(b));
}
__device__ __forceinline__ float2 unpack2(unsigned long long v) {
    float2 f;
    asm("mov.b64 {%0, %1}, %2;" : "=f"(f.x), "=f"(f.y) : "l"(v));
    return f;
}

// ---------------------------------------------------------------------------
// GEMM: Wh = fp16(feat @ W + b), both relations (blockIdx.y). Side stream.
// ---------------------------------------------------------------------------
__global__ __launch_bounds__(128) void gemm_kernel(
    const float* __restrict__ feat,
    const float* __restrict__ W0, const float* __restrict__ b0,
    const float* __restrict__ W1, const float* __restrict__ b1)
{
    const int rel = blockIdx.y;
    const float* __restrict__ W = rel ? W1 : W0;
    const float* __restrict__ b = rel ? b1 : b0;
    __half* __restrict__ Wh = rel ? g_Wh1 : g_Wh0;

    __shared__ __align__(16) float sft[D][GROWS + 2];
    const int tid  = threadIdx.x;
    const int row0 = blockIdx.x * GROWS;

    for (int i = tid; i < GROWS * (D / 4); i += 128) {
        const int r  = i >> 5;
        const int c4 = i & 31;
        const int grow = row0 + r;
        float4 v = make_float4(0.f, 0.f, 0.f, 0.f);
        if (grow < N_NODES)
            v = reinterpret_cast<const float4*>(feat + (size_t)grow * D)[c4];
        sft[4 * c4 + 0][r] = v.x;
        sft[4 * c4 + 1][r] = v.y;
        sft[4 * c4 + 2][r] = v.z;
        sft[4 * c4 + 3][r] = v.w;
    }
    __syncthreads();

    unsigned long long acc[16];
#pragma unroll
    for (int r = 0; r < 16; r++) acc[r] = 0ull;

    const float* __restrict__ Wcol = W + tid;
#pragma unroll 4
    for (int k = 0; k < D; k++) {
        const float w = __ldg(Wcol + (size_t)k * D);
        const unsigned long long w2 = pack2(w, w);
        const unsigned long long* arow =
            reinterpret_cast<const unsigned long long*>(&sft[k][0]);
#pragma unroll
        for (int r = 0; r < 16; r++)
            fma2(acc[r], arow[r], w2);
    }

    const float bias = __ldg(b + tid);
#pragma unroll
    for (int r = 0; r < 16; r++) {
        const float2 v = unpack2(acc[r]);
        const int g0 = row0 + 2 * r;
        if (g0 < N_NODES)
            Wh[(size_t)g0 * D + tid] = __float2half(v.x + bias);
        if (g0 + 1 < N_NODES)
            Wh[(size_t)(g0 + 1) * D + tid] = __float2half(v.y + bias);
    }
}

// ---------------------------------------------------------------------------
// Histogram of dst per relation — 4 edges/thread via int4 for MLP.
// ---------------------------------------------------------------------------
__global__ __launch_bounds__(256) void hist_kernel(
    const int* __restrict__ dst0, const int* __restrict__ dst1)
{
    const int e0 = (blockIdx.x * blockDim.x + threadIdx.x) * 4;
    if (e0 >= E_EDGES) return;        // E divisible by 4
    const int* __restrict__ dst = blockIdx.y ? dst1 : dst0;
    int* __restrict__ cnt = blockIdx.y ? g_cnt1 : g_cnt0;
    const int4 d = __ldg(reinterpret_cast<const int4*>(dst + e0));
    atomicAdd(&cnt[d.x], 1);
    atomicAdd(&cnt[d.y], 1);
    atomicAdd(&cnt[d.z], 1);
    atomicAdd(&cnt[d.w], 1);
}

// ---------------------------------------------------------------------------
// Parallel scan, phase 1: per-block sums.
// ---------------------------------------------------------------------------
__global__ __launch_bounds__(SCAN_B) void scan1_kernel() {
    const int rel = blockIdx.y;
    const int* __restrict__ cnt = rel ? g_cnt1 : g_cnt0;
    int* __restrict__ bsum = rel ? g_bsum1 : g_bsum0;

    const int i = blockIdx.x * SCAN_B + threadIdx.x;
    int x = (i < N_NODES) ? cnt[i] : 0;
#pragma unroll
    for (int o = 16; o; o >>= 1) x += __shfl_down_sync(0xffffffffu, x, o);

    __shared__ int ws[SCAN_B / 32];
    const int lane = threadIdx.x & 31, wid = threadIdx.x >> 5;
    if (lane == 0) ws[wid] = x;
    __syncthreads();
    if (wid == 0) {
        int t = (lane < SCAN_B / 32) ? ws[lane] : 0;
#pragma unroll
        for (int o = 16; o; o >>= 1) t += __shfl_down_sync(0xffffffffu, t, o);
        if (lane == 0) bsum[blockIdx.x] = t;
    }
}

// ---------------------------------------------------------------------------
// Phase 2: exclusive scan of NBLK block sums.
// ---------------------------------------------------------------------------
__global__ __launch_bounds__(128) void scan2_kernel() {
    int* __restrict__ bsum = blockIdx.x ? g_bsum1 : g_bsum0;
    __shared__ int buf[128];
    const int tid = threadIdx.x;
    const int x = (tid < NBLK) ? bsum[tid] : 0;
    buf[tid] = x;
    __syncthreads();
#pragma unroll
    for (int o = 1; o < 128; o <<= 1) {
        int v = (tid >= o) ? buf[tid - o] : 0;
        __syncthreads();
        buf[tid] += v;
        __syncthreads();
    }
    if (tid < NBLK) bsum[tid] = buf[tid] - x;
}

// ---------------------------------------------------------------------------
// Phase 3: local exclusive scan + block offset -> offs, cur.
// ---------------------------------------------------------------------------
__global__ __launch_bounds__(SCAN_B) void scan3_kernel() {
    const int rel = blockIdx.y;
    const int* __restrict__ cnt = rel ? g_cnt1 : g_cnt0;
    const int* __restrict__ bsum = rel ? g_bsum1 : g_bsum0;
    int* __restrict__ offs = rel ? g_offs1 : g_offs0;
    int* __restrict__ cur  = rel ? g_cur1  : g_cur0;

    const int i = blockIdx.x * SCAN_B + threadIdx.x;
    const int x = (i < N_NODES) ? cnt[i] : 0;
    const int lane = threadIdx.x & 31, wid = threadIdx.x >> 5;

    int s = x;
#pragma unroll
    for (int o = 1; o < 32; o <<= 1) {
        int t = __shfl_up_sync(0xffffffffu, s, o);
        if (lane >= o) s += t;
    }
    __shared__ int ws[SCAN_B / 32];
    if (lane == 31) ws[wid] = s;
    __syncthreads();
    if (wid == 0) {
        int t = (lane < SCAN_B / 32) ? ws[lane] : 0;
#pragma unroll
        for (int o = 1; o < 32; o <<= 1) {
            int u = __shfl_up_sync(0xffffffffu, t, o);
            if (lane >= o) t += u;
        }
        if (lane < SCAN_B / 32) ws[lane] = t;
    }
    __syncthreads();
    const int prefix = (wid > 0) ? ws[wid - 1] : 0;
    const int excl = bsum[blockIdx.x] + prefix + s - x;
    if (i < N_NODES) { offs[i] = excl; cur[i] = excl; }
    if (i == N_NODES - 1) offs[N_NODES] = E_EDGES;
}

// ---------------------------------------------------------------------------
// Fill sorted-by-dst src lists — 4 edges/thread via int4 for MLP.
// ---------------------------------------------------------------------------
__global__ __launch_bounds__(256) void fill_kernel(
    const int* __restrict__ src0, const int* __restrict__ dst0,
    const int* __restrict__ src1, const int* __restrict__ dst1)
{
    const int e0 = (blockIdx.x * blockDim.x + threadIdx.x) * 4;
    if (e0 >= E_EDGES) return;
    const int* __restrict__ src = blockIdx.y ? src1 : src0;
    const int* __restrict__ dst = blockIdx.y ? dst1 : dst0;
    int* __restrict__ cur = blockIdx.y ? g_cur1 : g_cur0;
    int* __restrict__ srt = blockIdx.y ? g_srt1 : g_srt0;

    const int4 d = __ldg(reinterpret_cast<const int4*>(dst + e0));
    const int4 s = __ldg(reinterpret_cast<const int4*>(src + e0));
    const int p0 = atomicAdd(&cur[d.x], 1);
    const int p1 = atomicAdd(&cur[d.y], 1);
    const int p2 = atomicAdd(&cur[d.z], 1);
    const int p3 = atomicAdd(&cur[d.w], 1);
    srt[p0] = s.x; srt[p1] = s.y; srt[p2] = s.z; srt[p3] = s.w;
}

// ---------------------------------------------------------------------------
// Warp-per-node pull gather over fp16 Wh. Lane covers 4 cols (8B loads).
// ---------------------------------------------------------------------------
__device__ __forceinline__ void acc_u2(float4& a, uint2 u) {
    const __half2 h0 = *reinterpret_cast<__half2*>(&u.x);
    const __half2 h1 = *reinterpret_cast<__half2*>(&u.y);
    const float2 f0 = __half22float2(h0);
    const float2 f1 = __half22float2(h1);
    a.x += f0.x; a.y += f0.y; a.z += f1.x; a.w += f1.y;
}

__device__ __forceinline__ uint2 ld_row_h(const __half* __restrict__ Wh,
                                          int s, int lane) {
    return __ldg(reinterpret_cast<const uint2*>(Wh + (size_t)s * D) + lane);
}

__device__ __forceinline__ float4 gather_rel(
    const __half* __restrict__ Wh, const int* __restrict__ srt,
    int beg, int end, int lane)
{
    float4 acc = make_float4(0.f, 0.f, 0.f, 0.f);
    int e = beg;
    for (; e + 4 <= end; e += 4) {
        const int s0 = __ldg(srt + e),     s1 = __ldg(srt + e + 1);
        const int s2 = __ldg(srt + e + 2), s3 = __ldg(srt + e + 3);
        const uint2 u0 = ld_row_h(Wh, s0, lane);
        const uint2 u1 = ld_row_h(Wh, s1, lane);
        const uint2 u2 = ld_row_h(Wh, s2, lane);
        const uint2 u3 = ld_row_h(Wh, s3, lane);
        acc_u2(acc, u0); acc_u2(acc, u1); acc_u2(acc, u2); acc_u2(acc, u3);
    }
    for (; e < end; e++)
        acc_u2(acc, ld_row_h(Wh, __ldg(srt + e), lane));
    return acc;
}

__global__ __launch_bounds__(256) void gather_kernel(float* __restrict__ out) {
    const int n = blockIdx.x * 8 + (threadIdx.x >> 5);
    if (n >= N_NODES) return;
    const int lane = threadIdx.x & 31;

    const int b0 = g_offs0[n], e0 = g_offs0[n + 1];
    const int b1 = g_offs1[n], e1 = g_offs1[n + 1];

    const float4 a0 = gather_rel(g_Wh0, g_srt0, b0, e0, lane);
    const float4 a1 = gather_rel(g_Wh1, g_srt1, b1, e1, lane);

    const float inv0 = 1.0f / fmaxf((float)(e0 - b0), 1.0f);
    const float inv1 = 1.0f / fmaxf((float)(e1 - b1), 1.0f);

    float4 r;
    r.x = a0.x * inv0 + a1.x * inv1;
    r.y = a0.y * inv0 + a1.y * inv1;
    r.z = a0.z * inv0 + a1.z * inv1;
    r.w = a0.w * inv0 + a1.w * inv1;
    reinterpret_cast<float4*>(out + (size_t)n * D)[lane] = r;
}

// ---------------------------------------------------------------------------
// inputs: feat, W0, b0, W1, b1, src0, dst0, src1, dst1
// ---------------------------------------------------------------------------
extern "C" void kernel_launch(void* const* d_in, const int* in_sizes, int n_in,
                              void* d_out, int out_size) {
    const float* feat = (const float*)d_in[0];
    const float* W0   = (const float*)d_in[1];
    const float* b0   = (const float*)d_in[2];
    const float* W1   = (const float*)d_in[3];
    const float* b1   = (const float*)d_in[4];
    const int*   src0 = (const int*)d_in[5];
    const int*   dst0 = (const int*)d_in[6];
    const int*   src1 = (const int*)d_in[7];
    const int*   dst1 = (const int*)d_in[8];
    float* out = (float*)d_out;

    // Fork: GEMM on the side stream, concurrent with the CSR build.
    cudaEventRecord(g_ss.fork, 0);
    cudaStreamWaitEvent(g_ss.s, g_ss.fork, 0);
    dim3 ggrid((N_NODES + GROWS - 1) / GROWS, 2);
    gemm_kernel<<<ggrid, 128, 0, g_ss.s>>>(feat, W0, b0, W1, b1);
    cudaEventRecord(g_ss.join, g_ss.s);

    // Main stream: CSR build.
    void* cnt0_addr = nullptr; void* cnt1_addr = nullptr;
    cudaGetSymbolAddress(&cnt0_addr, g_cnt0);
    cudaGetSymbolAddress(&cnt1_addr, g_cnt1);
    cudaMemsetAsync(cnt0_addr, 0, N_NODES * sizeof(int), 0);
    cudaMemsetAsync(cnt1_addr, 0, N_NODES * sizeof(int), 0);

    dim3 egrid4((E_EDGES / 4 + 255) / 256, 2);
    hist_kernel<<<egrid4, 256>>>(dst0, dst1);

    dim3 sgrid(NBLK, 2);
    scan1_kernel<<<sgrid, SCAN_B>>>();
    scan2_kernel<<<2, 128>>>();
    scan3_kernel<<<sgrid, SCAN_B>>>();

    fill_kernel<<<egrid4, 256>>>(src0, dst0, src1, dst1);

    // Join, then gather.
    cudaStreamWaitEvent(0, g_ss.join, 0);
    gather_kernel<<<(N_NODES + 7) / 8, 256>>>(out);
}

// round 6
// speedup vs baseline: 3.4079x; 1.0052x over previous
#include <cuda_runtime.h>
#include <cuda_fp16.h>
#include <stdint.h>

#define N_NODES 50000
#define E_EDGES 800000
#define D 128
#define SCAN_B 512
#define NBLK ((N_NODES + SCAN_B - 1) / SCAN_B)   // 98
#define GTILES ((N_NODES + 127) / 128)           // 391
#define GS 136                                    // smem f16 stride (bank-safe)

// ---------------------------------------------------------------------------
// Scratch (__device__ globals; no allocations allowed).
// ---------------------------------------------------------------------------
__device__ __half g_Wh0[(size_t)N_NODES * D];
__device__ __half g_Wh1[(size_t)N_NODES * D];
__device__ int   g_cnt0[N_NODES];
__device__ int   g_cnt1[N_NODES];
__device__ int   g_offs0[N_NODES + 1];
__device__ int   g_offs1[N_NODES + 1];
__device__ int   g_cur0[N_NODES];
__device__ int   g_cur1[N_NODES];
__device__ int   g_srt0[E_EDGES];
__device__ int   g_srt1[E_EDGES];
__device__ int   g_bsum0[NBLK];
__device__ int   g_bsum1[NBLK];

// ---------------------------------------------------------------------------
// Host-side stream/event resources (created once; host-only resources).
// ---------------------------------------------------------------------------
struct SideStream {
    cudaStream_t s;
    cudaEvent_t  fork, join;
    SideStream() {
        cudaStreamCreateWithFlags(&s, cudaStreamNonBlocking);
        cudaEventCreateWithFlags(&fork, cudaEventDisableTiming);
        cudaEventCreateWithFlags(&join, cudaEventDisableTiming);
    }
};
static SideStream g_ss;

// ---------------------------------------------------------------------------
// Warp-level HMMA m16n8k16 (sm_80+ baseline PTX — compiles for compute_103).
// ---------------------------------------------------------------------------
__device__ __forceinline__ void mma16816(float* d,
                                         uint32_t a0, uint32_t a1,
                                         uint32_t a2, uint32_t a3,
                                         uint32_t b0, uint32_t b1) {
    asm volatile(
        "mma.sync.aligned.m16n8k16.row.col.f32.f16.f16.f32 "
        "{%0,%1,%2,%3}, {%4,%5,%6,%7}, {%8,%9}, {%0,%1,%2,%3};"
        : "+f"(d[0]), "+f"(d[1]), "+f"(d[2]), "+f"(d[3])
        : "r"(a0), "r"(a1), "r"(a2), "r"(a3), "r"(b0), "r"(b1));
}

// ---------------------------------------------------------------------------
// HMMA GEMM: Wh = fp16(feat @ W + b), Markidis hi/lo split (3 MMA terms).
// Block = 256 threads (8 warps), tile M=128 N=128 K=128 one-shot in smem.
// Warp w covers rows [w*16, w*16+16), all 128 cols. Runs on side stream.
// ---------------------------------------------------------------------------
__global__ __launch_bounds__(256, 1) void mma_gemm_kernel(
    const float* __restrict__ feat,
    const float* __restrict__ W0, const float* __restrict__ b0,
    const float* __restrict__ W1, const float* __restrict__ b1)
{
    extern __shared__ __align__(16) char smem[];
    __half* sAh = reinterpret_cast<__half*>(smem);          // [128][GS] feat hi
    __half* sAl = sAh + 128 * GS;                           // feat lo
    __half* sBh = sAl + 128 * GS;                           // Wt[n][k] hi
    __half* sBl = sBh + 128 * GS;                           // Wt lo

    const int rel = blockIdx.y;
    const float* __restrict__ W    = rel ? W1 : W0;
    const float* __restrict__ bias = rel ? b1 : b0;
    __half* __restrict__ Wh = rel ? g_Wh1 : g_Wh0;

    const int tid  = threadIdx.x;
    const int row0 = blockIdx.x * 128;

    // ---- W -> Wt hi/lo (read coalesced over n; transpose into smem) ----
    for (int i = tid; i < D * D; i += 256) {
        const int k = i >> 7, n = i & 127;
        const float w = __ldg(W + i);
        const __half h = __float2half_rn(w);
        const __half l = __float2half_rn(w - __half2float(h));
        sBh[n * GS + k] = h;
        sBl[n * GS + k] = l;
    }
    // ---- feat rows -> A hi/lo ----
    for (int i = tid; i < 128 * D; i += 256) {
        const int r = i >> 7, k = i & 127;
        const int gr = row0 + r;
        const float a = (gr < N_NODES) ? __ldg(feat + (size_t)gr * D + k) : 0.f;
        const __half h = __float2half_rn(a);
        const __half l = __float2half_rn(a - __half2float(h));
        sAh[r * GS + k] = h;
        sAl[r * GS + k] = l;
    }
    __syncthreads();

    // ---- MMA mainloop ----
    const int wid   = tid >> 5;
    const int lane  = tid & 31;
    const int group = lane >> 2;         // 0..7
    const int quad  = lane & 3;          // 0..3
    const int rA    = wid * 16 + group;  // A fragment row (local)

    float acc[16][4];
#pragma unroll
    for (int nt = 0; nt < 16; nt++)
#pragma unroll
        for (int j = 0; j < 4; j++) acc[nt][j] = 0.f;

#pragma unroll
    for (int kc = 0; kc < 8; kc++) {
        const int k0 = kc * 16 + quad * 2;
        const uint32_t ah0 = *reinterpret_cast<const uint32_t*>(&sAh[rA * GS + k0]);
        const uint32_t ah1 = *reinterpret_cast<const uint32_t*>(&sAh[(rA + 8) * GS + k0]);
        const uint32_t ah2 = *reinterpret_cast<const uint32_t*>(&sAh[rA * GS + k0 + 8]);
        const uint32_t ah3 = *reinterpret_cast<const uint32_t*>(&sAh[(rA + 8) * GS + k0 + 8]);
        const uint32_t al0 = *reinterpret_cast<const uint32_t*>(&sAl[rA * GS + k0]);
        const uint32_t al1 = *reinterpret_cast<const uint32_t*>(&sAl[(rA + 8) * GS + k0]);
        const uint32_t al2 = *reinterpret_cast<const uint32_t*>(&sAl[rA * GS + k0 + 8]);
        const uint32_t al3 = *reinterpret_cast<const uint32_t*>(&sAl[(rA + 8) * GS + k0 + 8]);
#pragma unroll
        for (int nt = 0; nt < 16; nt++) {
            const int n = nt * 8 + group;
            const uint32_t bh0 = *reinterpret_cast<const uint32_t*>(&sBh[n * GS + k0]);
            const uint32_t bh1 = *reinterpret_cast<const uint32_t*>(&sBh[n * GS + k0 + 8]);
            const uint32_t bl0 = *reinterpret_cast<const uint32_t*>(&sBl[n * GS + k0]);
            const uint32_t bl1 = *reinterpret_cast<const uint32_t*>(&sBl[n * GS + k0 + 8]);
            mma16816(acc[nt], ah0, ah1, ah2, ah3, bh0, bh1);   // Ah*Bh
            mma16816(acc[nt], ah0, ah1, ah2, ah3, bl0, bl1);   // Ah*Bl
            mma16816(acc[nt], al0, al1, al2, al3, bh0, bh1);   // Al*Bh
        }
    }

    // ---- Epilogue: bias add + fp16 store ----
    const int r0 = row0 + rA;
    const int r1 = r0 + 8;
#pragma unroll
    for (int nt = 0; nt < 16; nt++) {
        const int c = nt * 8 + quad * 2;
        const float bx = __ldg(bias + c);
        const float by = __ldg(bias + c + 1);
        if (r0 < N_NODES) {
            __half2 h = __floats2half2_rn(acc[nt][0] + bx, acc[nt][1] + by);
            *reinterpret_cast<uint32_t*>(Wh + (size_t)r0 * D + c) =
                *reinterpret_cast<uint32_t*>(&h);
        }
        if (r1 < N_NODES) {
            __half2 h = __floats2half2_rn(acc[nt][2] + bx, acc[nt][3] + by);
            *reinterpret_cast<uint32_t*>(Wh + (size_t)r1 * D + c) =
                *reinterpret_cast<uint32_t*>(&h);
        }
    }
}

#define GEMM_SMEM (4 * 128 * GS * (int)sizeof(__half))   // 139,264 B

// ---------------------------------------------------------------------------
// Histogram of dst per relation — 4 edges/thread via int4.
// ---------------------------------------------------------------------------
__global__ __launch_bounds__(256) void hist_kernel(
    const int* __restrict__ dst0, const int* __restrict__ dst1)
{
    const int e0 = (blockIdx.x * blockDim.x + threadIdx.x) * 4;
    if (e0 >= E_EDGES) return;
    const int* __restrict__ dst = blockIdx.y ? dst1 : dst0;
    int* __restrict__ cnt = blockIdx.y ? g_cnt1 : g_cnt0;
    const int4 d = __ldg(reinterpret_cast<const int4*>(dst + e0));
    atomicAdd(&cnt[d.x], 1);
    atomicAdd(&cnt[d.y], 1);
    atomicAdd(&cnt[d.z], 1);
    atomicAdd(&cnt[d.w], 1);
}

// ---------------------------------------------------------------------------
// Scan phase 1: per-block sums.
// ---------------------------------------------------------------------------
__global__ __launch_bounds__(SCAN_B) void scan1_kernel() {
    const int rel = blockIdx.y;
    const int* __restrict__ cnt = rel ? g_cnt1 : g_cnt0;
    int* __restrict__ bsum = rel ? g_bsum1 : g_bsum0;

    const int i = blockIdx.x * SCAN_B + threadIdx.x;
    int x = (i < N_NODES) ? cnt[i] : 0;
#pragma unroll
    for (int o = 16; o; o >>= 1) x += __shfl_down_sync(0xffffffffu, x, o);

    __shared__ int ws[SCAN_B / 32];
    const int lane = threadIdx.x & 31, wid = threadIdx.x >> 5;
    if (lane == 0) ws[wid] = x;
    __syncthreads();
    if (wid == 0) {
        int t = (lane < SCAN_B / 32) ? ws[lane] : 0;
#pragma unroll
        for (int o = 16; o; o >>= 1) t += __shfl_down_sync(0xffffffffu, t, o);
        if (lane == 0) bsum[blockIdx.x] = t;
    }
}

// ---------------------------------------------------------------------------
// Scan phase 2: exclusive scan of NBLK block sums.
// ---------------------------------------------------------------------------
__global__ __launch_bounds__(128) void scan2_kernel() {
    int* __restrict__ bsum = blockIdx.x ? g_bsum1 : g_bsum0;
    __shared__ int buf[128];
    const int tid = threadIdx.x;
    const int x = (tid < NBLK) ? bsum[tid] : 0;
    buf[tid] = x;
    __syncthreads();
#pragma unroll
    for (int o = 1; o < 128; o <<= 1) {
        int v = (tid >= o) ? buf[tid - o] : 0;
        __syncthreads();
        buf[tid] += v;
        __syncthreads();
    }
    if (tid < NBLK) bsum[tid] = buf[tid] - x;
}

// ---------------------------------------------------------------------------
// Scan phase 3: local exclusive scan + block offset -> offs, cur.
// ---------------------------------------------------------------------------
__global__ __launch_bounds__(SCAN_B) void scan3_kernel() {
    const int rel = blockIdx.y;
    const int* __restrict__ cnt = rel ? g_cnt1 : g_cnt0;
    const int* __restrict__ bsum = rel ? g_bsum1 : g_bsum0;
    int* __restrict__ offs = rel ? g_offs1 : g_offs0;
    int* __restrict__ cur  = rel ? g_cur1  : g_cur0;

    const int i = blockIdx.x * SCAN_B + threadIdx.x;
    const int x = (i < N_NODES) ? cnt[i] : 0;
    const int lane = threadIdx.x & 31, wid = threadIdx.x >> 5;

    int s = x;
#pragma unroll
    for (int o = 1; o < 32; o <<= 1) {
        int t = __shfl_up_sync(0xffffffffu, s, o);
        if (lane >= o) s += t;
    }
    __shared__ int ws[SCAN_B / 32];
    if (lane == 31) ws[wid] = s;
    __syncthreads();
    if (wid == 0) {
        int t = (lane < SCAN_B / 32) ? ws[lane] : 0;
#pragma unroll
        for (int o = 1; o < 32; o <<= 1) {
            int u = __shfl_up_sync(0xffffffffu, t, o);
            if (lane >= o) t += u;
        }
        if (lane < SCAN_B / 32) ws[lane] = t;
    }
    __syncthreads();
    const int prefix = (wid > 0) ? ws[wid - 1] : 0;
    const int excl = bsum[blockIdx.x] + prefix + s - x;
    if (i < N_NODES) { offs[i] = excl; cur[i] = excl; }
    if (i == N_NODES - 1) offs[N_NODES] = E_EDGES;
}

// ---------------------------------------------------------------------------
// Fill sorted-by-dst src lists — 4 edges/thread via int4.
// ---------------------------------------------------------------------------
__global__ __launch_bounds__(256) void fill_kernel(
    const int* __restrict__ src0, const int* __restrict__ dst0,
    const int* __restrict__ src1, const int* __restrict__ dst1)
{
    const int e0 = (blockIdx.x * blockDim.x + threadIdx.x) * 4;
    if (e0 >= E_EDGES) return;
    const int* __restrict__ src = blockIdx.y ? src1 : src0;
    const int* __restrict__ dst = blockIdx.y ? dst1 : dst0;
    int* __restrict__ cur = blockIdx.y ? g_cur1 : g_cur0;
    int* __restrict__ srt = blockIdx.y ? g_srt1 : g_srt0;

    const int4 d = __ldg(reinterpret_cast<const int4*>(dst + e0));
    const int4 s = __ldg(reinterpret_cast<const int4*>(src + e0));
    const int p0 = atomicAdd(&cur[d.x], 1);
    const int p1 = atomicAdd(&cur[d.y], 1);
    const int p2 = atomicAdd(&cur[d.z], 1);
    const int p3 = atomicAdd(&cur[d.w], 1);
    srt[p0] = s.x; srt[p1] = s.y; srt[p2] = s.z; srt[p3] = s.w;
}

// ---------------------------------------------------------------------------
// Warp-per-node pull gather over fp16 Wh.
// ---------------------------------------------------------------------------
__device__ __forceinline__ void acc_u2(float4& a, uint2 u) {
    const __half2 h0 = *reinterpret_cast<__half2*>(&u.x);
    const __half2 h1 = *reinterpret_cast<__half2*>(&u.y);
    const float2 f0 = __half22float2(h0);
    const float2 f1 = __half22float2(h1);
    a.x += f0.x; a.y += f0.y; a.z += f1.x; a.w += f1.y;
}
__device__ __forceinline__ uint2 ld_row_h(const __half* __restrict__ Wh,
                                          int s, int lane) {
    return __ldg(reinterpret_cast<const uint2*>(Wh + (size_t)s * D) + lane);
}
__device__ __forceinline__ float4 gather_rel(
    const __half* __restrict__ Wh, const int* __restrict__ srt,
    int beg, int end, int lane)
{
    float4 acc = make_float4(0.f, 0.f, 0.f, 0.f);
    int e = beg;
    for (; e + 4 <= end; e += 4) {
        const int s0 = __ldg(srt + e),     s1 = __ldg(srt + e + 1);
        const int s2 = __ldg(srt + e + 2), s3 = __ldg(srt + e + 3);
        const uint2 u0 = ld_row_h(Wh, s0, lane);
        const uint2 u1 = ld_row_h(Wh, s1, lane);
        const uint2 u2 = ld_row_h(Wh, s2, lane);
        const uint2 u3 = ld_row_h(Wh, s3, lane);
        acc_u2(acc, u0); acc_u2(acc, u1); acc_u2(acc, u2); acc_u2(acc, u3);
    }
    for (; e < end; e++)
        acc_u2(acc, ld_row_h(Wh, __ldg(srt + e), lane));
    return acc;
}

__global__ __launch_bounds__(256) void gather_kernel(float* __restrict__ out) {
    const int n = blockIdx.x * 8 + (threadIdx.x >> 5);
    if (n >= N_NODES) return;
    const int lane = threadIdx.x & 31;

    const int b0 = g_offs0[n], e0 = g_offs0[n + 1];
    const int b1 = g_offs1[n], e1 = g_offs1[n + 1];

    const float4 a0 = gather_rel(g_Wh0, g_srt0, b0, e0, lane);
    const float4 a1 = gather_rel(g_Wh1, g_srt1, b1, e1, lane);

    const float inv0 = 1.0f / fmaxf((float)(e0 - b0), 1.0f);
    const float inv1 = 1.0f / fmaxf((float)(e1 - b1), 1.0f);

    float4 r;
    r.x = a0.x * inv0 + a1.x * inv1;
    r.y = a0.y * inv0 + a1.y * inv1;
    r.z = a0.z * inv0 + a1.z * inv1;
    r.w = a0.w * inv0 + a1.w * inv1;
    reinterpret_cast<float4*>(out + (size_t)n * D)[lane] = r;
}

// ---------------------------------------------------------------------------
// inputs: feat, W0, b0, W1, b1, src0, dst0, src1, dst1
// ---------------------------------------------------------------------------
extern "C" void kernel_launch(void* const* d_in, const int* in_sizes, int n_in,
                              void* d_out, int out_size) {
    const float* feat = (const float*)d_in[0];
    const float* W0   = (const float*)d_in[1];
    const float* b0   = (const float*)d_in[2];
    const float* W1   = (const float*)d_in[3];
    const float* b1   = (const float*)d_in[4];
    const int*   src0 = (const int*)d_in[5];
    const int*   dst0 = (const int*)d_in[6];
    const int*   src1 = (const int*)d_in[7];
    const int*   dst1 = (const int*)d_in[8];
    float* out = (float*)d_out;

    cudaFuncSetAttribute(mma_gemm_kernel,
                         cudaFuncAttributeMaxDynamicSharedMemorySize, GEMM_SMEM);

    // Fork: HMMA GEMM on the side stream, concurrent with the CSR build.
    cudaEventRecord(g_ss.fork, 0);
    cudaStreamWaitEvent(g_ss.s, g_ss.fork, 0);
    dim3 ggrid(GTILES, 2);
    mma_gemm_kernel<<<ggrid, 256, GEMM_SMEM, g_ss.s>>>(feat, W0, b0, W1, b1);
    cudaEventRecord(g_ss.join, g_ss.s);

    // Main stream: CSR build.
    void* cnt0_addr = nullptr; void* cnt1_addr = nullptr;
    cudaGetSymbolAddress(&cnt0_addr, g_cnt0);
    cudaGetSymbolAddress(&cnt1_addr, g_cnt1);
    cudaMemsetAsync(cnt0_addr, 0, N_NODES * sizeof(int), 0);
    cudaMemsetAsync(cnt1_addr, 0, N_NODES * sizeof(int), 0);

    dim3 egrid4((E_EDGES / 4 + 255) / 256, 2);
    hist_kernel<<<egrid4, 256>>>(dst0, dst1);

    dim3 sgrid(NBLK, 2);
    scan1_kernel<<<sgrid, SCAN_B>>>();
    scan2_kernel<<<2, 128>>>();
    scan3_kernel<<<sgrid, SCAN_B>>>();

    fill_kernel<<<egrid4, 256>>>(src0, dst0, src1, dst1);

    // Join, then gather.
    cudaStreamWaitEvent(0, g_ss.join, 0);
    gather_kernel<<<(N_NODES + 7) / 8, 256>>>(out);
}